// round 3
// baseline (speedup 1.0000x reference)
#include <cuda_runtime.h>
#include <cstdint>

#define NTOT 32768
#define DSUB 128
#define SCB  1024
#define KCB  4
#define MT   128
#define ST   128
#define NCHUNK (SCB/ST)
#define THREADS 256
#define ATS 136                       /* transposed-A d-slice stride (floats) */

#define IDX_CNT (NTOT*KCB)            /* 131072  */
#define ZQ_CNT  (NTOT*KCB*DSUB)       /* 16777216 */
#define SC_OFF  (IDX_CNT + 2*ZQ_CNT)  /* 33685504 */

// smem layout (floats): At[128*136] | Bs0[128*128] | Bs1[128*128] | sIdx[128] | Xs[128]
#define SM_AT   0
#define SM_BS0  (DSUB*ATS)
#define SM_BS1  (SM_BS0 + DSUB*ST)
#define SM_IDX  (SM_BS1 + DSUB*ST)
#define SM_XS   (SM_IDX + MT)
#define SMEM_FLOATS (SM_XS + MT)
#define SMEM_BYTES  (SMEM_FLOATS*4)

__device__ double g_loss;
__device__ float  g_counts[KCB*SCB];
__device__ float  g_cnorm[KCB*SCB];
__device__ float  g_ct[KCB*DSUB*SCB];   // transposed codebooks: [k][d][s]

__device__ __forceinline__ void cpa16(float* dst, const float* src) {
    unsigned sa = (unsigned)__cvta_generic_to_shared(dst);
    asm volatile("cp.async.cg.shared.global [%0], [%1], 16;" :: "r"(sa), "l"(src));
}

__global__ void init_kernel(const float* __restrict__ cb) {
    int t = blockIdx.x*blockDim.x + threadIdx.x;
    if (t == 0) g_loss = 0.0;
    if (t < KCB*SCB) {
        g_counts[t] = 0.f;
        // ||c||^2: STRICT sequential ascending d, UNFUSED mul+add (XLA elemental reduce)
        const float* r = cb + (size_t)t*DSUB;
        float s = 0.f;
        #pragma unroll 8
        for (int i = 0; i < DSUB; i++) {
            float v = r[i];
            s = __fadd_rn(s, __fmul_rn(v, v));
        }
        g_cnorm[t] = s;
    }
    const int tot = KCB*DSUB*SCB;
    for (int o = t; o < tot; o += blockDim.x*gridDim.x) {
        int s = o & (SCB-1);
        int d = (o >> 10) & (DSUB-1);
        int k = o >> 17;
        g_ct[o] = cb[((k*SCB + s)*DSUB) + d];
    }
}

__global__ __launch_bounds__(THREADS, 1)
void vq_kernel(const float* __restrict__ ze, const float* __restrict__ cb,
               float* __restrict__ out) {
    extern __shared__ float smem[];
    float* At  = smem + SM_AT;
    float* Bs0 = smem + SM_BS0;
    float* Bs1 = smem + SM_BS1;
    int*   sIdx = (int*)(smem + SM_IDX);
    float* Xs  = smem + SM_XS;
    __shared__ float red[8];

    const int k   = blockIdx.y;
    const int tid = threadIdx.x;
    const int n0  = blockIdx.x * MT;
    const int tx  = tid & 15;     // 16 col-groups (8 cols each: 4*tx+j / 64+4*tx+j)
    const int ty  = tid >> 4;     // 16 row-groups (8 rows each)

    // ---- kick off B chunk 0 (pre-transposed: conflict-free direct copy) ----
    {
        const float* src = g_ct + (size_t)k*DSUB*SCB;
        for (int t = tid; t < (DSUB*ST)/4; t += THREADS) {
            int d = t >> 5, q = t & 31;
            cpa16(Bs0 + d*ST + q*4, src + d*SCB + q*4);
        }
        asm volatile("cp.async.commit_group;" ::: "memory");
    }
    // ---- load A tile TRANSPOSED: At[d*ATS + row]; STS conflict-free (row varies in warp)
    {
        int row = tid & 127;
        int d40 = tid >> 7;                 // 0 or 1
        const float* zr = ze + (size_t)(n0 + row)*512 + k*DSUB;
        #pragma unroll
        for (int d4 = d40; d4 < 32; d4 += 2) {
            float4 v = *(const float4*)(zr + 4*d4);
            At[(4*d4+0)*ATS + row] = v.x;
            At[(4*d4+1)*ATS + row] = v.y;
            At[(4*d4+2)*ATS + row] = v.z;
            At[(4*d4+3)*ATS + row] = v.w;
        }
    }
    __syncthreads();

    // ---- X[row] = ||x||^2, STRICT sequential ascending d, UNFUSED (emulate ref) ----
    if (tid < MT) {
        float s = 0.f;
        #pragma unroll 8
        for (int d = 0; d < DSUB; d++) {
            float v = At[d*ATS + tid];      // conflict-free: distinct rows per warp
            s = __fadd_rn(s, __fmul_rn(v, v));
        }
        Xs[tid] = s;
    }
    __syncthreads();

    float Xr[8];
    #pragma unroll
    for (int i = 0; i < 8; i++) Xr[i] = Xs[ty*8 + i];

    float bestV[8];
    int   bestI[8];
    #pragma unroll
    for (int i = 0; i < 8; i++) { bestV[i] = 3.402823466e38f; bestI[i] = 0; }

    const float* cn = g_cnorm + k*SCB;

    for (int c = 0; c < NCHUNK; c++) {
        float* Bc = (c & 1) ? Bs1 : Bs0;
        if (c + 1 < NCHUNK) {
            const float* src = g_ct + (size_t)k*DSUB*SCB + (c+1)*ST;
            float* dstB = ((c+1) & 1) ? Bs1 : Bs0;
            for (int t = tid; t < (DSUB*ST)/4; t += THREADS) {
                int d = t >> 5, q = t & 31;
                cpa16(dstB + d*ST + q*4, src + d*SCB + q*4);
            }
            asm volatile("cp.async.commit_group;" ::: "memory");
            asm volatile("cp.async.wait_group 1;" ::: "memory");
        } else {
            asm volatile("cp.async.wait_group 0;" ::: "memory");
        }
        __syncthreads();

        float cnr[8];
        #pragma unroll
        for (int j = 0; j < 8; j++) {
            int col = (j < 4) ? (4*tx + j) : (64 + 4*tx + (j - 4));
            cnr[j] = cn[c*ST + col];
        }

        // acc[p][j]: f32x2 over ROW pair (8ty+2p, 8ty+2p+1), column j
        unsigned long long acc[4][8];
        #pragma unroll
        for (int p = 0; p < 4; p++)
            #pragma unroll
            for (int j = 0; j < 8; j++) acc[p][j] = 0ULL;

        #pragma unroll 2
        for (int kk = 0; kk < DSUB; kk++) {
            // a row-pairs: direct vector loads, no dup needed
            const float* atk = At + kk*ATS + ty*8;
            ulonglong2 aLo = *(const ulonglong2*)(atk);       // pairs (r0,r1),(r2,r3)
            ulonglong2 aHi = *(const ulonglong2*)(atk + 4);   // pairs (r4,r5),(r6,r7)
            unsigned long long ap[4] = { aLo.x, aLo.y, aHi.x, aHi.y };
            // b scalars for 8 cols, duplicated into f32x2
            float4 b0 = *(const float4*)(Bc + kk*ST + 4*tx);
            float4 b1 = *(const float4*)(Bc + kk*ST + 64 + 4*tx);
            unsigned long long bd[8];
            asm("mov.b64 %0, {%1, %1};" : "=l"(bd[0]) : "f"(b0.x));
            asm("mov.b64 %0, {%1, %1};" : "=l"(bd[1]) : "f"(b0.y));
            asm("mov.b64 %0, {%1, %1};" : "=l"(bd[2]) : "f"(b0.z));
            asm("mov.b64 %0, {%1, %1};" : "=l"(bd[3]) : "f"(b0.w));
            asm("mov.b64 %0, {%1, %1};" : "=l"(bd[4]) : "f"(b1.x));
            asm("mov.b64 %0, {%1, %1};" : "=l"(bd[5]) : "f"(b1.y));
            asm("mov.b64 %0, {%1, %1};" : "=l"(bd[6]) : "f"(b1.z));
            asm("mov.b64 %0, {%1, %1};" : "=l"(bd[7]) : "f"(b1.w));
            #pragma unroll
            for (int p = 0; p < 4; p++)
                #pragma unroll
                for (int j = 0; j < 8; j++)
                    asm("fma.rn.f32x2 %0, %1, %2, %0;" : "+l"(acc[p][j]) : "l"(ap[p]), "l"(bd[j]));
        }

        // dist = fl( fl(X - fl(2*G)) + C ), emulating ref's rounding; argmin strict <
        #pragma unroll
        for (int p = 0; p < 4; p++) {
            #pragma unroll
            for (int j = 0; j < 8; j++) {
                float lo, hi;
                asm("mov.b64 {%0, %1}, %2;" : "=f"(lo), "=f"(hi) : "l"(acc[p][j]));
                int col = (j < 4) ? (4*tx + j) : (64 + 4*tx + (j - 4));
                int g0 = c*ST + col;
                int rLo = 2*p, rHi = 2*p + 1;
                float s0 = __fadd_rn(__fsub_rn(Xr[rLo], __fmul_rn(2.0f, lo)), cnr[j]);
                float s1 = __fadd_rn(__fsub_rn(Xr[rHi], __fmul_rn(2.0f, hi)), cnr[j]);
                if (s0 < bestV[rLo]) { bestV[rLo] = s0; bestI[rLo] = g0; }
                if (s1 < bestV[rHi]) { bestV[rHi] = s1; bestI[rHi] = g0; }
            }
        }
        __syncthreads();
    }

    // ---- cross-lane argmin over the 16 col-groups (index tiebreak = lowest) ----
    #pragma unroll
    for (int i = 0; i < 8; i++) {
        float v = bestV[i]; int id = bestI[i];
        #pragma unroll
        for (int off = 1; off < 16; off <<= 1) {
            float vo = __shfl_xor_sync(0xffffffffu, v, off);
            int io   = __shfl_xor_sync(0xffffffffu, id, off);
            if (vo < v || (vo == v && io < id)) { v = vo; id = io; }
        }
        if (tx == 0) {
            int row = ty*8 + i;
            sIdx[row] = id;
            out[(n0 + row)*KCB + k] = (float)id;   // indices_all[n][k]
        }
    }
    __syncthreads();

    if (tid < MT) atomicAdd(&g_counts[k*SCB + sIdx[tid]], 1.0f);

    // ---- epilogue: gather z_q, write both copies, accumulate loss ----
    float lsum = 0.f;
    const float* cbk = cb + (size_t)k*SCB*DSUB;
    float* o_st  = out + IDX_CNT;
    float* o_all = out + IDX_CNT + ZQ_CNT;
    for (int e = tid; e < MT*DSUB; e += THREADS) {
        int row = e >> 7, d = e & 127;
        int idx = sIdx[row];
        float cv = __ldg(cbk + idx*DSUB + d);
        int go = (n0 + row)*512 + k*DSUB + d;
        float a = ze[go];
        float diff = __fsub_rn(cv, a);        // fp32, matches ref rounding
        o_st[go]  = __fadd_rn(a, diff);       // z_q_st = z_e + (z_q - z_e)
        o_all[go] = cv;                       // z_q_all
        lsum += diff*diff;
    }
    #pragma unroll
    for (int off = 16; off > 0; off >>= 1)
        lsum += __shfl_xor_sync(0xffffffffu, lsum, off);
    if ((tid & 31) == 0) red[tid >> 5] = lsum;
    __syncthreads();
    if (tid == 0) {
        float s = 0.f;
        #pragma unroll
        for (int w = 0; w < 8; w++) s += red[w];
        atomicAdd(&g_loss, (double)s);
    }
}

__global__ void fin_kernel(float* __restrict__ out) {
    __shared__ double sh[512];
    int tid = threadIdx.x;
    int k = tid >> 7, j = tid & 127;
    double h = 0.0;
    for (int s = j; s < SCB; s += 128) {
        float cnt = g_counts[k*SCB + s];
        if (cnt > 0.f) {
            double p = (double)cnt / (double)NTOT;
            h -= p * log(p);
        }
    }
    sh[tid] = h;
    __syncthreads();
    for (int off = 64; off > 0; off >>= 1) {
        if (j < off) sh[tid] += sh[tid + off];
        __syncthreads();
    }
    if (tid == 0) {
        double perp = 0.0;
        for (int kk = 0; kk < KCB; kk++) perp += exp(sh[kk*128]);
        perp *= 0.25;
        double loss = g_loss / (double)ZQ_CNT;
        out[SC_OFF + 0] = (float)loss;   // codebook_loss
        out[SC_OFF + 1] = (float)loss;   // commit_loss (same forward value)
        out[SC_OFF + 2] = (float)perp;   // perplexity
    }
}

extern "C" void kernel_launch(void* const* d_in, const int* in_sizes, int n_in,
                              void* d_out, int out_size) {
    const float* ze = (const float*)d_in[0];
    const float* cb = (const float*)d_in[1];
    if (n_in >= 2 && in_sizes[0] == KCB*SCB*DSUB && in_sizes[1] == NTOT*512) {
        const float* t = ze; ze = cb; cb = t;
    }
    float* out = (float*)d_out;
    (void)out_size;

    cudaFuncSetAttribute(vq_kernel, cudaFuncAttributeMaxDynamicSharedMemorySize, SMEM_BYTES);

    init_kernel<<<128, 256>>>(cb);
    vq_kernel<<<dim3(NTOT/MT, KCB), THREADS, SMEM_BYTES>>>(ze, cb, out);
    fin_kernel<<<1, 512>>>(out);
}